// round 7
// baseline (speedup 1.0000x reference)
#include <cuda_runtime.h>
#include <cstdint>

#define Tn     2048
#define Dn     512
#define Hn     512
#define HDn    256
#define NTAGS  20
#define STARTT 18
#define ENDT   19
#define NEGV   (-10000.0f)

#define CSIZE    8     // CTAs per direction (one cluster)
#define RTHREADS 512

// ---------------- scratch (static device memory; no allocations) ----------------
__device__ __align__(16) float g_xg[2][Tn * 1024];     // per-dir gate preactivations
__device__ __align__(16) float g_x1[Tn * Hn];          // layer0 output (concat f|b)
__device__ __align__(16) float g_x2[Tn * Hn];          // layer1 output
__device__ __align__(16) float g_feats[Tn * NTAGS];
__device__ int g_tflags[2][2][16];                     // [layer][dir][mtile] n-block arrivals

// ---------------- PTX helpers ----------------
__device__ __forceinline__ uint32_t smem_u32(const void* p) {
    return (uint32_t)__cvta_generic_to_shared(p);
}

__device__ __forceinline__ void st_cluster_f32(uint32_t laddr, uint32_t rank, float v) {
    asm volatile("{\n\t"
        ".reg .b32 ra;\n\t"
        "mapa.shared::cluster.u32 ra, %0, %1;\n\t"
        "st.shared::cluster.f32 [ra], %2;\n\t"
        "}" :: "r"(laddr), "r"(rank), "f"(v) : "memory");
}

__device__ __forceinline__ void arrive_cluster(uint32_t laddr, uint32_t rank) {
    asm volatile("{\n\t"
        ".reg .b32 ra;\n\t"
        "mapa.shared::cluster.u32 ra, %0, %1;\n\t"
        "mbarrier.arrive.release.cluster.shared::cluster.b64 _, [ra];\n\t"
        "}" :: "r"(laddr), "r"(rank) : "memory");
}

__device__ __forceinline__ void mbar_wait_cluster(uint32_t addr, uint32_t parity) {
    uint32_t done;
    asm volatile("{\n\t"
        ".reg .pred p;\n\t"
        "mbarrier.try_wait.parity.acquire.cluster.shared::cta.b64 p, [%1], %2, 0x989680;\n\t"
        "selp.b32 %0, 1, 0, p;\n\t"
        "}" : "=r"(done) : "r"(addr), "r"(parity) : "memory");
    if (!done) {
        asm volatile("{\n\t"
            ".reg .pred P1;\n\t"
            "WAIT_LOOP_%=:\n\t"
            "mbarrier.try_wait.parity.acquire.cluster.shared::cta.b64 P1, [%0], %1, 0x989680;\n\t"
            "@P1 bra.uni WAIT_DONE_%=;\n\t"
            "bra.uni WAIT_LOOP_%=;\n\t"
            "WAIT_DONE_%=:\n\t"
            "}" :: "r"(addr), "r"(parity) : "memory");
    }
}

__device__ __forceinline__ void fma2(unsigned long long& acc,
                                     unsigned long long a, unsigned long long b) {
    asm("fma.rn.f32x2 %0, %1, %2, %0;" : "+l"(acc) : "l"(a), "l"(b));
}

__device__ __forceinline__ unsigned long long pk2(float lo, float hi) {
    unsigned long long r;
    asm("mov.b64 %0, {%1, %2};" : "=l"(r) : "f"(lo), "f"(hi));
    return r;
}

// fast, overflow-safe sigmoid/tanh (MUFU-based; validated rel_err 0.0)
__device__ __forceinline__ float fast_sig(float x) {
    return __fdividef(1.f, 1.f + __expf(-x));
}
__device__ __forceinline__ float fast_tanh(float x) {
    float e = __expf(2.f * fabsf(x));
    float t = 1.f - __fdividef(2.f, e + 1.f);
    return copysignf(t, x);
}

__global__ void zero_flags_kernel() {
    int* p = &g_tflags[0][0][0];
    if (threadIdx.x < 64) p[threadIdx.x] = 0;
}

// ---------------- GEMM: XG[dir] = X @ W^T + (bih + bhh), with tile flags ------
// Grid (8, 2, 16): x = n-tile, y = dir, z = mi (m-tiles in order [0,15,1,14,...]
// so both scan ends complete first). When sent != nullptr, A rows come from emb.
__global__ __launch_bounds__(256)
void gemm_kernel(int layer,
                 const float* __restrict__ A,
                 const int* __restrict__ sent, const float* __restrict__ emb,
                 const float* __restrict__ W0, const float* __restrict__ W1,
                 const float* __restrict__ bi0, const float* __restrict__ bh0,
                 const float* __restrict__ bi1, const float* __restrict__ bh1) {
    const int K = 512;
    int dir = blockIdx.y;
    int mi = blockIdx.z;
    int mt = (mi & 1) ? (15 - (mi >> 1)) : (mi >> 1);
    const float* B  = dir ? W1 : W0;
    const float* bi = dir ? bi1 : bi0;
    const float* bh = dir ? bh1 : bh0;
    float* C = g_xg[dir];

    __shared__ float As[8][128];
    __shared__ float Bs[8][128];

    int tid = threadIdx.x;
    int bm = mt * 128;
    int bn = blockIdx.x * 128;
    int lr = tid >> 1;
    int lc = (tid & 1) * 4;
    int tx = tid & 15;
    int ty = tid >> 4;

    unsigned long long acc[8][4];
#pragma unroll
    for (int i = 0; i < 8; i++)
#pragma unroll
        for (int j = 0; j < 4; j++) acc[i][j] = 0ull;

    long arow = bm + lr;
    const float* Asrc = A;
    if (sent) { arow = __ldg(&sent[bm + lr]); Asrc = emb; }
    const float* Ap = Asrc + arow * K + lc;
    const float* Bp = B + (long)(bn + lr) * K + lc;

    for (int k0 = 0; k0 < K; k0 += 8) {
        float4 av = *(const float4*)(Ap + k0);
        float4 bv = *(const float4*)(Bp + k0);
        As[lc + 0][lr] = av.x; As[lc + 1][lr] = av.y;
        As[lc + 2][lr] = av.z; As[lc + 3][lr] = av.w;
        Bs[lc + 0][lr] = bv.x; Bs[lc + 1][lr] = bv.y;
        Bs[lc + 2][lr] = bv.z; Bs[lc + 3][lr] = bv.w;
        __syncthreads();
#pragma unroll
        for (int kk = 0; kk < 8; kk++) {
            float4 a0 = *(const float4*)&As[kk][ty * 4];
            float4 a1 = *(const float4*)&As[kk][64 + ty * 4];
            float4 b0 = *(const float4*)&Bs[kk][tx * 4];
            float4 b1 = *(const float4*)&Bs[kk][64 + tx * 4];
            float a[8] = {a0.x, a0.y, a0.z, a0.w, a1.x, a1.y, a1.z, a1.w};
            unsigned long long pb[4];
            pb[0] = pk2(b0.x, b0.y); pb[1] = pk2(b0.z, b0.w);
            pb[2] = pk2(b1.x, b1.y); pb[3] = pk2(b1.z, b1.w);
#pragma unroll
            for (int i = 0; i < 8; i++) {
                unsigned long long pa = pk2(a[i], a[i]);
#pragma unroll
                for (int j = 0; j < 4; j++)
                    fma2(acc[i][j], pa, pb[j]);
            }
        }
        __syncthreads();
    }

#pragma unroll
    for (int i = 0; i < 8; i++) {
        int m = bm + ((i < 4) ? (ty * 4 + i) : (64 + ty * 4 + (i - 4)));
#pragma unroll
        for (int j = 0; j < 8; j++) {
            int n = bn + ((j < 4) ? (tx * 4 + j) : (64 + tx * 4 + (j - 4)));
            unsigned long long p = acc[i][j >> 1];
            float v = __uint_as_float((j & 1) ? (uint32_t)(p >> 32) : (uint32_t)p);
            C[(long)m * 1024 + n] = v + __ldg(&bi[n]) + __ldg(&bh[n]);
        }
    }

    // publish tile completion
    __threadfence();
    __syncthreads();
    if (tid == 0) atomicAdd(&g_tflags[layer][dir][mt], 1);
}

// ---------------- recurrence: cluster-of-8, hybrid funnel ---------------------
// Grid: 16 CTAs (2 clusters of 8). CTA rank owns cells [rank*32, rank*32+32).
// Warp w owns cells {2w, 2w+1}: gate rows colocated so the 4 gate z's are
// exchanged with 4 shuffles and ACTIVATIONS RUN IN PARALLEL across all 16
// warps (pre-barrier). Producers stage h locally (32 floats); after one
// __syncthreads, warp 0 alone broadcasts the 32 h values to all 8 CTAs and
// fires 8 arrives (barrier count stays 8 — narrow funnel, cheap barrier).
__global__ __launch_bounds__(RTHREADS, 1) __cluster_dims__(CSIZE, 1, 1)
void recur_kernel(int layer,
                  const float* __restrict__ Whh_f,
                  const float* __restrict__ Whh_b,
                  float* __restrict__ xnext) {
    __shared__ __align__(16) float hbuf[2][HDn];
    __shared__ float hstage[32];
    __shared__ __align__(8) unsigned long long bars[2];

    int dir = blockIdx.x / CSIZE;
    uint32_t rank;
    asm("mov.u32 %0, %%cluster_ctarank;" : "=r"(rank));
    int cbase = (int)rank * 32;

    int tid = threadIdx.x;
    int w = tid >> 5;
    int lane = tid & 31;
    int cell0 = cbase + 2 * w;          // first of this warp's two cells

    uint32_t bar0 = smem_u32(&bars[0]);
    uint32_t bar1 = smem_u32(&bars[1]);

    if (tid == 0) {
        asm volatile("mbarrier.init.shared.b64 [%0], %1;" :: "r"(bar0), "r"(CSIZE) : "memory");
        asm volatile("mbarrier.init.shared.b64 [%0], %1;" :: "r"(bar1), "r"(CSIZE) : "memory");
    }
    __syncthreads();
    asm volatile("barrier.cluster.arrive.aligned;" ::: "memory");
    asm volatile("barrier.cluster.wait.aligned;" ::: "memory");

    const float* Whh = dir ? Whh_b : Whh_f;
    const float* xg = g_xg[dir];

    // register-resident weights: row rr = gate(rr>>1) of cell (cell0 + (rr&1));
    // lane covers h columns [8*lane, 8*lane+8) packed as f32x2.
    ulonglong2 wreg[8][2];
#pragma unroll
    for (int rr = 0; rr < 8; rr++) {
        int grow = (rr >> 1) * HDn + cell0 + (rr & 1);
        const ulonglong2* wp = (const ulonglong2*)(Whh + (size_t)grow * HDn + lane * 8);
        wreg[rr][0] = wp[0];
        wreg[rr][1] = wp[1];
    }

    // after reduction, owner lane 4*rr holds row rr's sum
    bool owner4 = (lane & 3) == 0;
    int myrr = lane >> 2;
    int mygrow = (myrr >> 1) * HDn + cell0 + (myrr & 1);
    bool cellown = (lane == 0) | (lane == 4);   // lane 0 -> cell0, lane 4 -> cell0+1

    float c = 0.f;                               // valid in lanes 0,4

    for (int s = 0; s < Tn; s++) {
        int t = dir ? (Tn - 1 - s) : s;

        // per-tile gate on GEMM progress (once per 128 steps)
        if ((s & 127) == 0) {
            if (tid == 0) {
                int mt = dir ? (15 - (s >> 7)) : (s >> 7);
                volatile int* f = &g_tflags[layer][dir][mt];
                while (*f < 8) { }
                __threadfence();
            }
            __syncthreads();
        }

        // xg load issued before the barrier wait (latency overlapped)
        float xgv = owner4 ? __ldg(&xg[(size_t)t * 1024 + mygrow]) : 0.f;

        float z = 0.f;
        if (s > 0) {
            int pb = (s - 1) & 1;
            mbar_wait_cluster(pb ? bar1 : bar0, ((s - 1) >> 1) & 1);

            const ulonglong2* hp = (const ulonglong2*)&hbuf[pb][lane * 8];
            ulonglong2 h0 = hp[0];
            ulonglong2 h1 = hp[1];

            float srow[8];
#pragma unroll
            for (int rr = 0; rr < 8; rr++) {
                unsigned long long a = 0ull;
                fma2(a, wreg[rr][0].x, h0.x);
                fma2(a, wreg[rr][0].y, h0.y);
                fma2(a, wreg[rr][1].x, h1.x);
                fma2(a, wreg[rr][1].y, h1.y);
                float lo = __uint_as_float((uint32_t)a);
                float hi = __uint_as_float((uint32_t)(a >> 32));
                srow[rr] = lo + hi;
            }
            // butterfly reduce over 32 lanes with row-splitting (9 shfl)
#pragma unroll
            for (int i = 0; i < 4; i++) {
                float send = (lane & 16) ? srow[i] : srow[i + 4];
                float recv = __shfl_xor_sync(0xffffffffu, send, 16);
                srow[i] = ((lane & 16) ? srow[i + 4] : srow[i]) + recv;
            }
#pragma unroll
            for (int i = 0; i < 2; i++) {
                float send = (lane & 8) ? srow[i] : srow[i + 2];
                float recv = __shfl_xor_sync(0xffffffffu, send, 8);
                srow[i] = ((lane & 8) ? srow[i + 2] : srow[i]) + recv;
            }
            {
                float send = (lane & 4) ? srow[0] : srow[1];
                float recv = __shfl_xor_sync(0xffffffffu, send, 4);
                srow[0] = ((lane & 4) ? srow[1] : srow[0]) + recv;
            }
            srow[0] += __shfl_xor_sync(0xffffffffu, srow[0], 2);
            srow[0] += __shfl_xor_sync(0xffffffffu, srow[0], 1);
            z = srow[0];
        }
        z += xgv;

        // gate exchange: cell c gates live at owner lanes {0,8,16,24} + 4c
        int cg = lane & 4;
        float zi = __shfl_sync(0xffffffffu, z, cg);
        float zf = __shfl_sync(0xffffffffu, z, 8 + cg);
        float zg = __shfl_sync(0xffffffffu, z, 16 + cg);
        float zo = __shfl_sync(0xffffffffu, z, 24 + cg);

        if (cellown) {
            float ig = fast_sig(zi);
            float fg = fast_sig(zf);
            float og = fast_sig(zo);
            c = fg * c + ig * fast_tanh(zg);
            float h = og * fast_tanh(c);
            int jg = cell0 + (lane >> 2);             // global cell index
            xnext[(size_t)t * Hn + dir * HDn + jg] = h;
            hstage[2 * w + (lane >> 2)] = h;          // local staging for warp 0
        }
        __syncthreads();

        // narrow funnel: warp 0 broadcasts all 32 h values + 8 arrives
        if (tid < 32) {
            float h = hstage[lane];
            uint32_t dst = smem_u32(&hbuf[s & 1][cbase + lane]);
#pragma unroll
            for (int p = 0; p < CSIZE; p++) st_cluster_f32(dst, (uint32_t)p, h);
            __syncwarp();
            if (lane < CSIZE) arrive_cluster((s & 1) ? bar1 : bar0, (uint32_t)lane);
        }
    }

    asm volatile("barrier.cluster.arrive.aligned;" ::: "memory");
    asm volatile("barrier.cluster.wait.aligned;" ::: "memory");
}

// ---------------- projection: feats = x2 @ W_out^T + b_out ----------------
__global__ void proj_kernel(const float* __restrict__ Wout,
                            const float* __restrict__ bout) {
    int t = blockIdx.x;
    __shared__ float xs[Hn];
    int tid = threadIdx.x;   // 160
    for (int i = tid; i < Hn; i += 160) xs[i] = g_x2[(long)t * Hn + i];
    __syncthreads();
    int tag = tid >> 3;      // 0..19
    int p = tid & 7;
    float sum = 0.f;
    const float* wr = Wout + (long)tag * Hn + p * 64;
    const float* xr = xs + p * 64;
#pragma unroll
    for (int i = 0; i < 64; i++) sum = fmaf(__ldg(&wr[i]), xr[i], sum);
    sum += __shfl_xor_sync(0xffffffffu, sum, 1);
    sum += __shfl_xor_sync(0xffffffffu, sum, 2);
    sum += __shfl_xor_sync(0xffffffffu, sum, 4);
    if (p == 0) g_feats[t * NTAGS + tag] = sum + __ldg(&bout[tag]);
}

// ---------------- Viterbi: one warp, v in lane registers, bp in smem bytes ----
__global__ void viterbi_kernel(const float* __restrict__ trans,
                               float* __restrict__ out, int out_size) {
    __shared__ unsigned char bp[Tn][NTAGS];   // 40 KB
    int n = threadIdx.x;                       // 0..31
    bool act = (n < NTAGS);
    float tr[NTAGS];
#pragma unroll
    for (int p = 0; p < NTAGS; p++) tr[p] = act ? __ldg(&trans[n * NTAGS + p]) : 0.f;
    float trE = act ? __ldg(&trans[ENDT * NTAGS + n]) : 0.f;
    float v = act ? ((n == STARTT) ? 0.f : NEGV) : -1e30f;

    for (int t = 0; t < Tn; t++) {
        float feat = act ? __ldg(&g_feats[t * NTAGS + n]) : 0.f;
        float best = -1e30f;
        int arg = 0;
#pragma unroll
        for (int p = 0; p < NTAGS; p++) {
            float vp = __shfl_sync(0xffffffffu, v, p);
            float sc = vp + tr[p];
            if (sc > best) { best = sc; arg = p; }   // strict > => first-index argmax
        }
        v = best + feat;
        if (act) bp[t][n] = (unsigned char)arg;
    }

    float term = act ? (v + trE) : -1e30f;
    int idx = act ? n : 31;
#pragma unroll
    for (int off = 16; off; off >>= 1) {
        float ov = __shfl_xor_sync(0xffffffffu, term, off);
        int oi = __shfl_xor_sync(0xffffffffu, idx, off);
        if (ov > term || (ov == term && oi < idx)) { term = ov; idx = oi; }
    }
    __syncwarp();

    if (n == 0) {
        if (out_size > 0) out[0] = term;
        int tag = idx;
        for (int t = Tn - 1; t >= 0; t--) {
            if (1 + t < out_size) out[1 + t] = (float)tag;
            tag = bp[t][tag];
        }
        for (int i = Tn + 1; i < out_size; i++) out[i] = 0.f;
    }
}

// ---------------- launch ----------------
extern "C" void kernel_launch(void* const* d_in, const int* in_sizes, int n_in,
                              void* d_out, int out_size) {
    const int*   sent    = (const int*)d_in[0];
    const float* emb     = (const float*)d_in[1];
    const float* l0f_Wih = (const float*)d_in[2];
    const float* l0f_Whh = (const float*)d_in[3];
    const float* l0f_bih = (const float*)d_in[4];
    const float* l0f_bhh = (const float*)d_in[5];
    const float* l0b_Wih = (const float*)d_in[6];
    const float* l0b_Whh = (const float*)d_in[7];
    const float* l0b_bih = (const float*)d_in[8];
    const float* l0b_bhh = (const float*)d_in[9];
    const float* l1f_Wih = (const float*)d_in[10];
    const float* l1f_Whh = (const float*)d_in[11];
    const float* l1f_bih = (const float*)d_in[12];
    const float* l1f_bhh = (const float*)d_in[13];
    const float* l1b_Wih = (const float*)d_in[14];
    const float* l1b_Whh = (const float*)d_in[15];
    const float* l1b_bih = (const float*)d_in[16];
    const float* l1b_bhh = (const float*)d_in[17];
    const float* W_out   = (const float*)d_in[18];
    const float* b_out   = (const float*)d_in[19];
    const float* trans   = (const float*)d_in[20];
    float* out = (float*)d_out;

    static float* s_x1 = nullptr;
    static float* s_x2 = nullptr;
    static cudaStream_t s1 = nullptr;
    static cudaEvent_t ev0 = nullptr, ev1 = nullptr, ev2 = nullptr;
    if (!s_x1) {
        cudaGetSymbolAddress((void**)&s_x1, g_x1);
        cudaGetSymbolAddress((void**)&s_x2, g_x2);
        cudaStreamCreateWithFlags(&s1, cudaStreamNonBlocking);
        cudaEventCreateWithFlags(&ev0, cudaEventDisableTiming);
        cudaEventCreateWithFlags(&ev1, cudaEventDisableTiming);
        cudaEventCreateWithFlags(&ev2, cudaEventDisableTiming);
    }

    dim3 ggrid(8, 2, 16);   // n-tile, dir, mi (interleaved m-tiles)

    // stream 0 (captured): zero flags, then recurrences
    zero_flags_kernel<<<1, 64>>>();
    cudaEventRecord(ev0, 0);
    cudaStreamWaitEvent(s1, ev0, 0);

    // GEMM0 on side stream, concurrent with recur0 (flag-gated per tile)
    gemm_kernel<<<ggrid, 256, 0, s1>>>(0, nullptr, sent, emb, l0f_Wih, l0b_Wih,
                                       l0f_bih, l0f_bhh, l0b_bih, l0b_bhh);
    recur_kernel<<<2 * CSIZE, RTHREADS>>>(0, l0f_Whh, l0b_Whh, s_x1);

    // GEMM1 must wait for x1 (recur0 done), then runs concurrent with recur1
    cudaEventRecord(ev1, 0);
    cudaStreamWaitEvent(s1, ev1, 0);
    gemm_kernel<<<ggrid, 256, 0, s1>>>(1, s_x1, nullptr, nullptr, l1f_Wih, l1b_Wih,
                                       l1f_bih, l1f_bhh, l1b_bih, l1b_bhh);
    cudaEventRecord(ev2, s1);

    recur_kernel<<<2 * CSIZE, RTHREADS>>>(1, l1f_Whh, l1b_Whh, s_x2);

    // join side stream back before epilogue
    cudaStreamWaitEvent(0, ev2, 0);
    proj_kernel<<<Tn, 160>>>(W_out, b_out);
    viterbi_kernel<<<1, 32>>>(trans, out, out_size);
}

// round 8
// speedup vs baseline: 1.1191x; 1.1191x over previous
#include <cuda_runtime.h>
#include <cstdint>

#define Tn     2048
#define Dn     512
#define Hn     512
#define HDn    256
#define NTAGS  20
#define STARTT 18
#define ENDT   19
#define NEGV   (-10000.0f)

#define CSIZE    8     // CTAs per direction (one cluster)
#define RTHREADS 512

// ---------------- scratch (static device memory; no allocations) ----------------
__device__ __align__(16) float g_xg[2][Tn * 1024];     // per-dir gate preactivations
__device__ __align__(16) float g_x1[Tn * Hn];          // layer0 output (concat f|b)
__device__ __align__(16) float g_x2[Tn * Hn];          // layer1 output
__device__ __align__(16) float g_feats[Tn * NTAGS];
__device__ int g_tflags[2][2][16];                     // [layer][dir][mtile] n-block arrivals

// ---------------- PTX helpers ----------------
__device__ __forceinline__ uint32_t smem_u32(const void* p) {
    return (uint32_t)__cvta_generic_to_shared(p);
}

__device__ __forceinline__ void st_cluster_f32(uint32_t laddr, uint32_t rank, float v) {
    asm volatile("{\n\t"
        ".reg .b32 ra;\n\t"
        "mapa.shared::cluster.u32 ra, %0, %1;\n\t"
        "st.shared::cluster.f32 [ra], %2;\n\t"
        "}" :: "r"(laddr), "r"(rank), "f"(v) : "memory");
}

__device__ __forceinline__ void arrive_cluster(uint32_t laddr, uint32_t rank) {
    asm volatile("{\n\t"
        ".reg .b32 ra;\n\t"
        "mapa.shared::cluster.u32 ra, %0, %1;\n\t"
        "mbarrier.arrive.release.cluster.shared::cluster.b64 _, [ra];\n\t"
        "}" :: "r"(laddr), "r"(rank) : "memory");
}

__device__ __forceinline__ void mbar_wait_cluster(uint32_t addr, uint32_t parity) {
    uint32_t done;
    asm volatile("{\n\t"
        ".reg .pred p;\n\t"
        "mbarrier.try_wait.parity.acquire.cluster.shared::cta.b64 p, [%1], %2, 0x989680;\n\t"
        "selp.b32 %0, 1, 0, p;\n\t"
        "}" : "=r"(done) : "r"(addr), "r"(parity) : "memory");
    if (!done) {
        asm volatile("{\n\t"
            ".reg .pred P1;\n\t"
            "WAIT_LOOP_%=:\n\t"
            "mbarrier.try_wait.parity.acquire.cluster.shared::cta.b64 P1, [%0], %1, 0x989680;\n\t"
            "@P1 bra.uni WAIT_DONE_%=;\n\t"
            "bra.uni WAIT_LOOP_%=;\n\t"
            "WAIT_DONE_%=:\n\t"
            "}" :: "r"(addr), "r"(parity) : "memory");
    }
}

__device__ __forceinline__ void fma2(unsigned long long& acc,
                                     unsigned long long a, unsigned long long b) {
    asm("fma.rn.f32x2 %0, %1, %2, %0;" : "+l"(acc) : "l"(a), "l"(b));
}

__device__ __forceinline__ unsigned long long pk2(float lo, float hi) {
    unsigned long long r;
    asm("mov.b64 %0, {%1, %2};" : "=l"(r) : "f"(lo), "f"(hi));
    return r;
}

// single-instruction MUFU.TANH (sm_75+); sigmoid via tanh identity
__device__ __forceinline__ float tanh_apx(float x) {
    float r;
    asm("tanh.approx.f32 %0, %1;" : "=f"(r) : "f"(x));
    return r;
}
__device__ __forceinline__ float sig_apx(float x) {
    return fmaf(0.5f, tanh_apx(0.5f * x), 0.5f);
}

__global__ void zero_flags_kernel() {
    int* p = &g_tflags[0][0][0];
    if (threadIdx.x < 64) p[threadIdx.x] = 0;
}

// ---------------- GEMM: XG[dir] = X @ W^T + (bih + bhh), with tile flags ------
// Grid (8, 2, 16): x = n-tile, y = dir, z = mi (m-tiles in order [0,15,1,14,...]
// so both scan ends complete first). When sent != nullptr, A rows come from emb.
__global__ __launch_bounds__(256)
void gemm_kernel(int layer,
                 const float* __restrict__ A,
                 const int* __restrict__ sent, const float* __restrict__ emb,
                 const float* __restrict__ W0, const float* __restrict__ W1,
                 const float* __restrict__ bi0, const float* __restrict__ bh0,
                 const float* __restrict__ bi1, const float* __restrict__ bh1) {
    const int K = 512;
    int dir = blockIdx.y;
    int mi = blockIdx.z;
    int mt = (mi & 1) ? (15 - (mi >> 1)) : (mi >> 1);
    const float* B  = dir ? W1 : W0;
    const float* bi = dir ? bi1 : bi0;
    const float* bh = dir ? bh1 : bh0;
    float* C = g_xg[dir];

    __shared__ float As[8][128];
    __shared__ float Bs[8][128];

    int tid = threadIdx.x;
    int bm = mt * 128;
    int bn = blockIdx.x * 128;
    int lr = tid >> 1;
    int lc = (tid & 1) * 4;
    int tx = tid & 15;
    int ty = tid >> 4;

    unsigned long long acc[8][4];
#pragma unroll
    for (int i = 0; i < 8; i++)
#pragma unroll
        for (int j = 0; j < 4; j++) acc[i][j] = 0ull;

    long arow = bm + lr;
    const float* Asrc = A;
    if (sent) { arow = __ldg(&sent[bm + lr]); Asrc = emb; }
    const float* Ap = Asrc + arow * K + lc;
    const float* Bp = B + (long)(bn + lr) * K + lc;

    for (int k0 = 0; k0 < K; k0 += 8) {
        float4 av = *(const float4*)(Ap + k0);
        float4 bv = *(const float4*)(Bp + k0);
        As[lc + 0][lr] = av.x; As[lc + 1][lr] = av.y;
        As[lc + 2][lr] = av.z; As[lc + 3][lr] = av.w;
        Bs[lc + 0][lr] = bv.x; Bs[lc + 1][lr] = bv.y;
        Bs[lc + 2][lr] = bv.z; Bs[lc + 3][lr] = bv.w;
        __syncthreads();
#pragma unroll
        for (int kk = 0; kk < 8; kk++) {
            float4 a0 = *(const float4*)&As[kk][ty * 4];
            float4 a1 = *(const float4*)&As[kk][64 + ty * 4];
            float4 b0 = *(const float4*)&Bs[kk][tx * 4];
            float4 b1 = *(const float4*)&Bs[kk][64 + tx * 4];
            float a[8] = {a0.x, a0.y, a0.z, a0.w, a1.x, a1.y, a1.z, a1.w};
            unsigned long long pb[4];
            pb[0] = pk2(b0.x, b0.y); pb[1] = pk2(b0.z, b0.w);
            pb[2] = pk2(b1.x, b1.y); pb[3] = pk2(b1.z, b1.w);
#pragma unroll
            for (int i = 0; i < 8; i++) {
                unsigned long long pa = pk2(a[i], a[i]);
#pragma unroll
                for (int j = 0; j < 4; j++)
                    fma2(acc[i][j], pa, pb[j]);
            }
        }
        __syncthreads();
    }

#pragma unroll
    for (int i = 0; i < 8; i++) {
        int m = bm + ((i < 4) ? (ty * 4 + i) : (64 + ty * 4 + (i - 4)));
#pragma unroll
        for (int j = 0; j < 8; j++) {
            int n = bn + ((j < 4) ? (tx * 4 + j) : (64 + tx * 4 + (j - 4)));
            unsigned long long p = acc[i][j >> 1];
            float v = __uint_as_float((j & 1) ? (uint32_t)(p >> 32) : (uint32_t)p);
            C[(long)m * 1024 + n] = v + __ldg(&bi[n]) + __ldg(&bh[n]);
        }
    }

    // publish tile completion
    __threadfence();
    __syncthreads();
    if (tid == 0) atomicAdd(&g_tflags[layer][dir][mt], 1);
}

// ---------------- recurrence: cluster-of-8 per direction (R5 structure) -------
// Grid: 16 CTAs (2 clusters of 8). CTA rank owns cells [rank*32, rank*32+32)
// => 128 gate rows. Warp w owns local rows 8w..8w+7; lane l owns h cols 8l..8l+7.
// Warp 0 funnel: activations via MUFU.TANH, DSMEM broadcast + arrive FIRST,
// then the xnext global store (off the release-ordered critical path).
__global__ __launch_bounds__(RTHREADS, 1) __cluster_dims__(CSIZE, 1, 1)
void recur_kernel(int layer,
                  const float* __restrict__ Whh_f,
                  const float* __restrict__ Whh_b,
                  float* __restrict__ xnext) {
    __shared__ __align__(16) float hbuf[2][HDn];
    __shared__ float zs[128];
    __shared__ __align__(8) unsigned long long bars[2];

    int dir = blockIdx.x / CSIZE;
    uint32_t rank;
    asm("mov.u32 %0, %%cluster_ctarank;" : "=r"(rank));
    int cbase = (int)rank * 32;

    int tid = threadIdx.x;
    int w = tid >> 5;
    int lane = tid & 31;

    uint32_t bar0 = smem_u32(&bars[0]);
    uint32_t bar1 = smem_u32(&bars[1]);

    if (tid == 0) {
        asm volatile("mbarrier.init.shared.b64 [%0], %1;" :: "r"(bar0), "r"(CSIZE) : "memory");
        asm volatile("mbarrier.init.shared.b64 [%0], %1;" :: "r"(bar1), "r"(CSIZE) : "memory");
    }
    __syncthreads();
    asm volatile("barrier.cluster.arrive.aligned;" ::: "memory");
    asm volatile("barrier.cluster.wait.aligned;" ::: "memory");

    // row owned by this lane after the reduction
    int rofs = (((lane >> 4) & 1) << 2) | (((lane >> 3) & 1) << 1) | ((lane >> 2) & 1);
    int lrow_mine = w * 8 + rofs;                      // 0..127
    int grow_mine = (lrow_mine >> 5) * HDn + cbase + (lrow_mine & 31);
    bool is_owner = ((lane & 3) == 0);

    const float* Whh = dir ? Whh_b : Whh_f;
    const float* xg = g_xg[dir];

    // register-resident weights: rows 8w..8w+7, cols 8*lane..8*lane+7, packed f32x2
    ulonglong2 wreg[8][2];
#pragma unroll
    for (int r = 0; r < 8; r++) {
        int lr = w * 8 + r;
        int grow = (lr >> 5) * HDn + cbase + (lr & 31);
        const ulonglong2* wp = (const ulonglong2*)(Whh + (size_t)grow * HDn + lane * 8);
        wreg[r][0] = wp[0];
        wreg[r][1] = wp[1];
    }

    float c = 0.f;   // valid in tid<32

    for (int s = 0; s < Tn; s++) {
        int t = dir ? (Tn - 1 - s) : s;

        // per-tile gate on GEMM progress (once per 128 steps)
        if ((s & 127) == 0) {
            if (tid == 0) {
                int mt = dir ? (15 - (s >> 7)) : (s >> 7);
                volatile int* f = &g_tflags[layer][dir][mt];
                while (*f < 8) { }
                __threadfence();
            }
            __syncthreads();
        }

        // xg load issued before the barrier wait (latency overlapped)
        float xgv = 0.f;
        if (is_owner) xgv = __ldg(&xg[(size_t)t * 1024 + grow_mine]);

        float sum = 0.f;
        if (s > 0) {
            int pb = (s - 1) & 1;
            mbar_wait_cluster(pb ? bar1 : bar0, ((s - 1) >> 1) & 1);

            const ulonglong2* hp = (const ulonglong2*)&hbuf[pb][lane * 8];
            ulonglong2 h0 = hp[0];
            ulonglong2 h1 = hp[1];

            float srow[8];
#pragma unroll
            for (int r = 0; r < 8; r++) {
                unsigned long long a = 0ull;
                fma2(a, wreg[r][0].x, h0.x);
                fma2(a, wreg[r][0].y, h0.y);
                fma2(a, wreg[r][1].x, h1.x);
                fma2(a, wreg[r][1].y, h1.y);
                float lo = __uint_as_float((uint32_t)a);
                float hi = __uint_as_float((uint32_t)(a >> 32));
                srow[r] = lo + hi;
            }
            // butterfly reduce over 32 lanes with row-splitting (9 shfl)
#pragma unroll
            for (int i = 0; i < 4; i++) {
                float send = (lane & 16) ? srow[i] : srow[i + 4];
                float recv = __shfl_xor_sync(0xffffffffu, send, 16);
                srow[i] = ((lane & 16) ? srow[i + 4] : srow[i]) + recv;
            }
#pragma unroll
            for (int i = 0; i < 2; i++) {
                float send = (lane & 8) ? srow[i] : srow[i + 2];
                float recv = __shfl_xor_sync(0xffffffffu, send, 8);
                srow[i] = ((lane & 8) ? srow[i + 2] : srow[i]) + recv;
            }
            {
                float send = (lane & 4) ? srow[0] : srow[1];
                float recv = __shfl_xor_sync(0xffffffffu, send, 4);
                srow[0] = ((lane & 4) ? srow[1] : srow[0]) + recv;
            }
            srow[0] += __shfl_xor_sync(0xffffffffu, srow[0], 2);
            srow[0] += __shfl_xor_sync(0xffffffffu, srow[0], 1);
            sum = srow[0];
        }

        if (is_owner) zs[lrow_mine] = sum + xgv;
        __syncthreads();

        if (tid < 32) {
            int j = tid;
            float zi = zs[j];
            float zf = zs[32 + j];
            float zg = zs[64 + j];
            float zo = zs[96 + j];
            float ig = sig_apx(zi);
            float fg = sig_apx(zf);
            float og = sig_apx(zo);
            c = fg * c + ig * tanh_apx(zg);
            float h = og * tanh_apx(c);

            // broadcast h into every cluster CTA's hbuf[s&1] FIRST
            uint32_t dst = smem_u32(&hbuf[s & 1][cbase + j]);
#pragma unroll
            for (int p = 0; p < CSIZE; p++) st_cluster_f32(dst, (uint32_t)p, h);
            __syncwarp();
            if (tid < CSIZE) arrive_cluster((s & 1) ? bar1 : bar0, (uint32_t)tid);

            // global store AFTER the arrives (not covered by the release)
            xnext[(size_t)t * Hn + dir * HDn + cbase + j] = h;
        }
    }

    asm volatile("barrier.cluster.arrive.aligned;" ::: "memory");
    asm volatile("barrier.cluster.wait.aligned;" ::: "memory");
}

// ---------------- projection: feats = x2 @ W_out^T + b_out ----------------
__global__ void proj_kernel(const float* __restrict__ Wout,
                            const float* __restrict__ bout) {
    int t = blockIdx.x;
    __shared__ float xs[Hn];
    int tid = threadIdx.x;   // 160
    for (int i = tid; i < Hn; i += 160) xs[i] = g_x2[(long)t * Hn + i];
    __syncthreads();
    int tag = tid >> 3;      // 0..19
    int p = tid & 7;
    float sum = 0.f;
    const float* wr = Wout + (long)tag * Hn + p * 64;
    const float* xr = xs + p * 64;
#pragma unroll
    for (int i = 0; i < 64; i++) sum = fmaf(__ldg(&wr[i]), xr[i], sum);
    sum += __shfl_xor_sync(0xffffffffu, sum, 1);
    sum += __shfl_xor_sync(0xffffffffu, sum, 2);
    sum += __shfl_xor_sync(0xffffffffu, sum, 4);
    if (p == 0) g_feats[t * NTAGS + tag] = sum + __ldg(&bout[tag]);
}

// ---------------- Viterbi: one warp; feats preloaded into smem; tree argmax ---
// Dynamic smem: feats copy (160 KB) + backpointers (40 KB).
#define VSMEM_BYTES (Tn * NTAGS * 4 + Tn * NTAGS)
__global__ void viterbi_kernel(const float* __restrict__ trans,
                               float* __restrict__ out, int out_size) {
    extern __shared__ unsigned char vsm[];
    float* fs = (float*)vsm;                          // [Tn][NTAGS]
    unsigned char* bp = vsm + Tn * NTAGS * 4;         // [Tn][NTAGS]

    int n = threadIdx.x;                              // 0..31
    // preload all feats into smem (L2-resident; off the sequential chain)
    for (int i = n; i < Tn * NTAGS; i += 32) fs[i] = __ldg(&g_feats[i]);

    bool act = (n < NTAGS);
    float tr[NTAGS];
#pragma unroll
    for (int p = 0; p < NTAGS; p++) tr[p] = act ? __ldg(&trans[n * NTAGS + p]) : 0.f;
    float trE = act ? __ldg(&trans[ENDT * NTAGS + n]) : 0.f;
    float v = act ? ((n == STARTT) ? 0.f : NEGV) : -1e30f;
    __syncwarp();

    for (int t = 0; t < Tn; t++) {
        // scores for this lane's target tag n over all predecessors p
        float sc[NTAGS];
#pragma unroll
        for (int p = 0; p < NTAGS; p++)
            sc[p] = __shfl_sync(0xffffffffu, v, p) + tr[p];

        // adjacent-pair argmax tree: a-side index < b-side index at every
        // level, so (va >= vb ? a : b) preserves first-index semantics.
        float mv[10]; int mi_[10];
#pragma unroll
        for (int i = 0; i < 10; i++) {
            bool left = sc[2 * i] >= sc[2 * i + 1];
            mv[i] = left ? sc[2 * i] : sc[2 * i + 1];
            mi_[i] = left ? 2 * i : 2 * i + 1;
        }
#pragma unroll
        for (int i = 0; i < 5; i++) {
            bool left = mv[2 * i] >= mv[2 * i + 1];
            mv[i] = left ? mv[2 * i] : mv[2 * i + 1];
            mi_[i] = left ? mi_[2 * i] : mi_[2 * i + 1];
        }
        // 5 -> 3 (pairs (0,1),(2,3), carry 4)
        {
            bool l0 = mv[0] >= mv[1];
            float v0 = l0 ? mv[0] : mv[1]; int i0 = l0 ? mi_[0] : mi_[1];
            bool l1 = mv[2] >= mv[3];
            float v1 = l1 ? mv[2] : mv[3]; int i1 = l1 ? mi_[2] : mi_[3];
            bool l2 = v0 >= v1;
            float v2 = l2 ? v0 : v1; int i2 = l2 ? i0 : i1;
            bool l3 = v2 >= mv[4];
            mv[0] = l3 ? v2 : mv[4]; mi_[0] = l3 ? i2 : mi_[4];
        }
        float feat = act ? fs[t * NTAGS + n] : 0.f;
        v = mv[0] + feat;
        if (act) bp[t * NTAGS + n] = (unsigned char)mi_[0];
    }

    float term = act ? (v + trE) : -1e30f;
    int idx = act ? n : 31;
#pragma unroll
    for (int off = 16; off; off >>= 1) {
        float ov = __shfl_xor_sync(0xffffffffu, term, off);
        int oi = __shfl_xor_sync(0xffffffffu, idx, off);
        if (ov > term || (ov == term && oi < idx)) { term = ov; idx = oi; }
    }
    __syncwarp();

    if (n == 0) {
        if (out_size > 0) out[0] = term;
        int tag = idx;
        for (int t = Tn - 1; t >= 0; t--) {
            if (1 + t < out_size) out[1 + t] = (float)tag;
            tag = bp[t * NTAGS + tag];
        }
        for (int i = Tn + 1; i < out_size; i++) out[i] = 0.f;
    }
}

// ---------------- launch ----------------
extern "C" void kernel_launch(void* const* d_in, const int* in_sizes, int n_in,
                              void* d_out, int out_size) {
    const int*   sent    = (const int*)d_in[0];
    const float* emb     = (const float*)d_in[1];
    const float* l0f_Wih = (const float*)d_in[2];
    const float* l0f_Whh = (const float*)d_in[3];
    const float* l0f_bih = (const float*)d_in[4];
    const float* l0f_bhh = (const float*)d_in[5];
    const float* l0b_Wih = (const float*)d_in[6];
    const float* l0b_Whh = (const float*)d_in[7];
    const float* l0b_bih = (const float*)d_in[8];
    const float* l0b_bhh = (const float*)d_in[9];
    const float* l1f_Wih = (const float*)d_in[10];
    const float* l1f_Whh = (const float*)d_in[11];
    const float* l1f_bih = (const float*)d_in[12];
    const float* l1f_bhh = (const float*)d_in[13];
    const float* l1b_Wih = (const float*)d_in[14];
    const float* l1b_Whh = (const float*)d_in[15];
    const float* l1b_bih = (const float*)d_in[16];
    const float* l1b_bhh = (const float*)d_in[17];
    const float* W_out   = (const float*)d_in[18];
    const float* b_out   = (const float*)d_in[19];
    const float* trans   = (const float*)d_in[20];
    float* out = (float*)d_out;

    static float* s_x1 = nullptr;
    static float* s_x2 = nullptr;
    static cudaStream_t s1 = nullptr;
    static cudaEvent_t ev0 = nullptr, ev1 = nullptr, ev2 = nullptr;
    if (!s_x1) {
        cudaGetSymbolAddress((void**)&s_x1, g_x1);
        cudaGetSymbolAddress((void**)&s_x2, g_x2);
        cudaStreamCreateWithFlags(&s1, cudaStreamNonBlocking);
        cudaEventCreateWithFlags(&ev0, cudaEventDisableTiming);
        cudaEventCreateWithFlags(&ev1, cudaEventDisableTiming);
        cudaEventCreateWithFlags(&ev2, cudaEventDisableTiming);
        cudaFuncSetAttribute(viterbi_kernel,
                             cudaFuncAttributeMaxDynamicSharedMemorySize, VSMEM_BYTES);
    }

    dim3 ggrid(8, 2, 16);   // n-tile, dir, mi (interleaved m-tiles)

    // stream 0 (captured): zero flags, then recurrences
    zero_flags_kernel<<<1, 64>>>();
    cudaEventRecord(ev0, 0);
    cudaStreamWaitEvent(s1, ev0, 0);

    // GEMM0 on side stream, concurrent with recur0 (flag-gated per tile)
    gemm_kernel<<<ggrid, 256, 0, s1>>>(0, nullptr, sent, emb, l0f_Wih, l0b_Wih,
                                       l0f_bih, l0f_bhh, l0b_bih, l0b_bhh);
    recur_kernel<<<2 * CSIZE, RTHREADS>>>(0, l0f_Whh, l0b_Whh, s_x1);

    // GEMM1 must wait for x1 (recur0 done), then runs concurrent with recur1
    cudaEventRecord(ev1, 0);
    cudaStreamWaitEvent(s1, ev1, 0);
    gemm_kernel<<<ggrid, 256, 0, s1>>>(1, s_x1, nullptr, nullptr, l1f_Wih, l1b_Wih,
                                       l1f_bih, l1f_bhh, l1b_bih, l1b_bhh);
    cudaEventRecord(ev2, s1);

    recur_kernel<<<2 * CSIZE, RTHREADS>>>(1, l1f_Whh, l1b_Whh, s_x2);

    // join side stream back before epilogue
    cudaStreamWaitEvent(0, ev2, 0);
    proj_kernel<<<Tn, 160>>>(W_out, b_out);
    viterbi_kernel<<<1, 32, VSMEM_BYTES>>>(trans, out, out_size);
}

// round 9
// speedup vs baseline: 1.1417x; 1.0202x over previous
#include <cuda_runtime.h>
#include <cstdint>

#define Tn     2048
#define Dn     512
#define Hn     512
#define HDn    256
#define NTAGS  20
#define STARTT 18
#define ENDT   19
#define NEGV   (-10000.0f)

#define CSIZE    16    // CTAs per direction (one nonportable cluster)
#define RTHREADS 512

// ---------------- scratch (static device memory; no allocations) ----------------
__device__ __align__(16) float g_xg[2][Tn * 1024];     // per-dir gate preactivations
__device__ __align__(16) float g_x1[Tn * Hn];          // layer0 output (concat f|b)
__device__ __align__(16) float g_x2[Tn * Hn];          // layer1 output
__device__ __align__(16) float g_feats[Tn * NTAGS];
__device__ int g_tflags[2][2][16];                     // [layer][dir][mtile] n-block arrivals

// ---------------- PTX helpers ----------------
__device__ __forceinline__ uint32_t smem_u32(const void* p) {
    return (uint32_t)__cvta_generic_to_shared(p);
}

__device__ __forceinline__ void st_cluster_f32(uint32_t laddr, uint32_t rank, float v) {
    asm volatile("{\n\t"
        ".reg .b32 ra;\n\t"
        "mapa.shared::cluster.u32 ra, %0, %1;\n\t"
        "st.shared::cluster.f32 [ra], %2;\n\t"
        "}" :: "r"(laddr), "r"(rank), "f"(v) : "memory");
}

__device__ __forceinline__ void arrive_cluster(uint32_t laddr, uint32_t rank) {
    asm volatile("{\n\t"
        ".reg .b32 ra;\n\t"
        "mapa.shared::cluster.u32 ra, %0, %1;\n\t"
        "mbarrier.arrive.release.cluster.shared::cluster.b64 _, [ra];\n\t"
        "}" :: "r"(laddr), "r"(rank) : "memory");
}

__device__ __forceinline__ void mbar_wait_cluster(uint32_t addr, uint32_t parity) {
    uint32_t done;
    asm volatile("{\n\t"
        ".reg .pred p;\n\t"
        "mbarrier.try_wait.parity.acquire.cluster.shared::cta.b64 p, [%1], %2, 0x989680;\n\t"
        "selp.b32 %0, 1, 0, p;\n\t"
        "}" : "=r"(done) : "r"(addr), "r"(parity) : "memory");
    if (!done) {
        asm volatile("{\n\t"
            ".reg .pred P1;\n\t"
            "WAIT_LOOP_%=:\n\t"
            "mbarrier.try_wait.parity.acquire.cluster.shared::cta.b64 P1, [%0], %1, 0x989680;\n\t"
            "@P1 bra.uni WAIT_DONE_%=;\n\t"
            "bra.uni WAIT_LOOP_%=;\n\t"
            "WAIT_DONE_%=:\n\t"
            "}" :: "r"(addr), "r"(parity) : "memory");
    }
}

__device__ __forceinline__ void fma2(unsigned long long& acc,
                                     unsigned long long a, unsigned long long b) {
    asm("fma.rn.f32x2 %0, %1, %2, %0;" : "+l"(acc) : "l"(a), "l"(b));
}

__device__ __forceinline__ unsigned long long pk2(float lo, float hi) {
    unsigned long long r;
    asm("mov.b64 %0, {%1, %2};" : "=l"(r) : "f"(lo), "f"(hi));
    return r;
}

// single-instruction MUFU.TANH (sm_75+); sigmoid via tanh identity
__device__ __forceinline__ float tanh_apx(float x) {
    float r;
    asm("tanh.approx.f32 %0, %1;" : "=f"(r) : "f"(x));
    return r;
}
__device__ __forceinline__ float sig_apx(float x) {
    return fmaf(0.5f, tanh_apx(0.5f * x), 0.5f);
}

__global__ void zero_flags_kernel() {
    int* p = &g_tflags[0][0][0];
    if (threadIdx.x < 64) p[threadIdx.x] = 0;
}

// ---------------- GEMM: XG[dir] = X @ W^T + (bih + bhh), with tile flags ------
// Grid (8, 2, 16): x = n-tile, y = dir, z = mi (m-tiles in order [0,15,1,14,...]
// so both scan ends complete first). When sent != nullptr, A rows come from emb.
__global__ __launch_bounds__(256)
void gemm_kernel(int layer,
                 const float* __restrict__ A,
                 const int* __restrict__ sent, const float* __restrict__ emb,
                 const float* __restrict__ W0, const float* __restrict__ W1,
                 const float* __restrict__ bi0, const float* __restrict__ bh0,
                 const float* __restrict__ bi1, const float* __restrict__ bh1) {
    const int K = 512;
    int dir = blockIdx.y;
    int mi = blockIdx.z;
    int mt = (mi & 1) ? (15 - (mi >> 1)) : (mi >> 1);
    const float* B  = dir ? W1 : W0;
    const float* bi = dir ? bi1 : bi0;
    const float* bh = dir ? bh1 : bh0;
    float* C = g_xg[dir];

    __shared__ float As[8][128];
    __shared__ float Bs[8][128];

    int tid = threadIdx.x;
    int bm = mt * 128;
    int bn = blockIdx.x * 128;
    int lr = tid >> 1;
    int lc = (tid & 1) * 4;
    int tx = tid & 15;
    int ty = tid >> 4;

    unsigned long long acc[8][4];
#pragma unroll
    for (int i = 0; i < 8; i++)
#pragma unroll
        for (int j = 0; j < 4; j++) acc[i][j] = 0ull;

    long arow = bm + lr;
    const float* Asrc = A;
    if (sent) { arow = __ldg(&sent[bm + lr]); Asrc = emb; }
    const float* Ap = Asrc + arow * K + lc;
    const float* Bp = B + (long)(bn + lr) * K + lc;

    for (int k0 = 0; k0 < K; k0 += 8) {
        float4 av = *(const float4*)(Ap + k0);
        float4 bv = *(const float4*)(Bp + k0);
        As[lc + 0][lr] = av.x; As[lc + 1][lr] = av.y;
        As[lc + 2][lr] = av.z; As[lc + 3][lr] = av.w;
        Bs[lc + 0][lr] = bv.x; Bs[lc + 1][lr] = bv.y;
        Bs[lc + 2][lr] = bv.z; Bs[lc + 3][lr] = bv.w;
        __syncthreads();
#pragma unroll
        for (int kk = 0; kk < 8; kk++) {
            float4 a0 = *(const float4*)&As[kk][ty * 4];
            float4 a1 = *(const float4*)&As[kk][64 + ty * 4];
            float4 b0 = *(const float4*)&Bs[kk][tx * 4];
            float4 b1 = *(const float4*)&Bs[kk][64 + tx * 4];
            float a[8] = {a0.x, a0.y, a0.z, a0.w, a1.x, a1.y, a1.z, a1.w};
            unsigned long long pb[4];
            pb[0] = pk2(b0.x, b0.y); pb[1] = pk2(b0.z, b0.w);
            pb[2] = pk2(b1.x, b1.y); pb[3] = pk2(b1.z, b1.w);
#pragma unroll
            for (int i = 0; i < 8; i++) {
                unsigned long long pa = pk2(a[i], a[i]);
#pragma unroll
                for (int j = 0; j < 4; j++)
                    fma2(acc[i][j], pa, pb[j]);
            }
        }
        __syncthreads();
    }

#pragma unroll
    for (int i = 0; i < 8; i++) {
        int m = bm + ((i < 4) ? (ty * 4 + i) : (64 + ty * 4 + (i - 4)));
#pragma unroll
        for (int j = 0; j < 8; j++) {
            int n = bn + ((j < 4) ? (tx * 4 + j) : (64 + tx * 4 + (j - 4)));
            unsigned long long p = acc[i][j >> 1];
            float v = __uint_as_float((j & 1) ? (uint32_t)(p >> 32) : (uint32_t)p);
            C[(long)m * 1024 + n] = v + __ldg(&bi[n]) + __ldg(&bh[n]);
        }
    }

    // publish tile completion
    __threadfence();
    __syncthreads();
    if (tid == 0) atomicAdd(&g_tflags[layer][dir][mt], 1);
}

// ---------------- recurrence: cluster-of-16 per direction --------------------
// Grid: 32 CTAs (2 nonportable clusters of 16). CTA rank owns cells
// [rank*16, rank*16+16) => 64 gate rows. Warp w owns local rows 4w..4w+3;
// lane l owns h cols 8l..8l+7. 6-shfl split reduction; owner lanes {0,8,16,24}.
// Warp-0 half-funnel (16 threads) does activations + 16-way DSMEM broadcast.
__global__ __launch_bounds__(RTHREADS, 1) __cluster_dims__(CSIZE, 1, 1)
void recur_kernel(int layer,
                  const float* __restrict__ Whh_f,
                  const float* __restrict__ Whh_b,
                  float* __restrict__ xnext) {
    __shared__ __align__(16) float hbuf[2][HDn];
    __shared__ float zs[64];
    __shared__ __align__(8) unsigned long long bars[2];

    int dir = blockIdx.x / CSIZE;
    uint32_t rank;
    asm("mov.u32 %0, %%cluster_ctarank;" : "=r"(rank));
    int cbase = (int)rank * 16;          // first cell owned by this CTA

    int tid = threadIdx.x;
    int w = tid >> 5;
    int lane = tid & 31;

    uint32_t bar0 = smem_u32(&bars[0]);
    uint32_t bar1 = smem_u32(&bars[1]);

    if (tid == 0) {
        asm volatile("mbarrier.init.shared.b64 [%0], %1;" :: "r"(bar0), "r"(CSIZE) : "memory");
        asm volatile("mbarrier.init.shared.b64 [%0], %1;" :: "r"(bar1), "r"(CSIZE) : "memory");
    }
    __syncthreads();
    asm volatile("barrier.cluster.arrive.aligned;" ::: "memory");
    asm volatile("barrier.cluster.wait.aligned;" ::: "memory");

    // owner mapping after the 6-shfl reduction: owner lanes are {0,8,16,24};
    // lane bit4 (16) -> row bit1, lane bit3 (8) -> row bit0.
    bool is_owner = (lane & 7) == 0;
    int myrr = lane >> 3;                               // 0..3 (owner lanes only)
    int lrow_mine = w * 4 + myrr;                       // 0..63
    int grow_mine = (lrow_mine >> 4) * HDn + cbase + (lrow_mine & 15);

    const float* Whh = dir ? Whh_b : Whh_f;
    const float* xg = g_xg[dir];

    // register-resident weights: rows 4w..4w+3, cols 8*lane..8*lane+7 (f32x2)
    ulonglong2 wreg[4][2];
#pragma unroll
    for (int r = 0; r < 4; r++) {
        int lr = w * 4 + r;
        int grow = (lr >> 4) * HDn + cbase + (lr & 15);
        const ulonglong2* wp = (const ulonglong2*)(Whh + (size_t)grow * HDn + lane * 8);
        wreg[r][0] = wp[0];
        wreg[r][1] = wp[1];
    }

    float c = 0.f;   // valid in tid<16

    for (int s = 0; s < Tn; s++) {
        int t = dir ? (Tn - 1 - s) : s;

        // per-tile gate on GEMM progress (once per 128 steps)
        if ((s & 127) == 0) {
            if (tid == 0) {
                int mt = dir ? (15 - (s >> 7)) : (s >> 7);
                volatile int* f = &g_tflags[layer][dir][mt];
                while (*f < 8) { }
                __threadfence();
            }
            __syncthreads();
        }

        // xg load issued before the barrier wait (latency overlapped)
        float xgv = 0.f;
        if (is_owner) xgv = __ldg(&xg[(size_t)t * 1024 + grow_mine]);

        float sum = 0.f;
        if (s > 0) {
            int pb = (s - 1) & 1;
            mbar_wait_cluster(pb ? bar1 : bar0, ((s - 1) >> 1) & 1);

            const ulonglong2* hp = (const ulonglong2*)&hbuf[pb][lane * 8];
            ulonglong2 h0 = hp[0];
            ulonglong2 h1 = hp[1];

            float srow[4];
#pragma unroll
            for (int r = 0; r < 4; r++) {
                unsigned long long a = 0ull;
                fma2(a, wreg[r][0].x, h0.x);
                fma2(a, wreg[r][0].y, h0.y);
                fma2(a, wreg[r][1].x, h1.x);
                fma2(a, wreg[r][1].y, h1.y);
                float lo = __uint_as_float((uint32_t)a);
                float hi = __uint_as_float((uint32_t)(a >> 32));
                srow[r] = lo + hi;
            }
            // split-butterfly reduce: 6 shfl total
#pragma unroll
            for (int i = 0; i < 2; i++) {
                float send = (lane & 16) ? srow[i] : srow[i + 2];
                float recv = __shfl_xor_sync(0xffffffffu, send, 16);
                srow[i] = ((lane & 16) ? srow[i + 2] : srow[i]) + recv;
            }
            {
                float send = (lane & 8) ? srow[0] : srow[1];
                float recv = __shfl_xor_sync(0xffffffffu, send, 8);
                srow[0] = ((lane & 8) ? srow[1] : srow[0]) + recv;
            }
            srow[0] += __shfl_xor_sync(0xffffffffu, srow[0], 4);
            srow[0] += __shfl_xor_sync(0xffffffffu, srow[0], 2);
            srow[0] += __shfl_xor_sync(0xffffffffu, srow[0], 1);
            sum = srow[0];
        }

        if (is_owner) zs[lrow_mine] = sum + xgv;
        __syncthreads();

        if (tid < 32) {
            float h = 0.f;
            if (lane < 16) {
                int j = lane;
                float zi = zs[j];
                float zf = zs[16 + j];
                float zg = zs[32 + j];
                float zo = zs[48 + j];
                float ig = sig_apx(zi);
                float fg = sig_apx(zf);
                float og = sig_apx(zo);
                c = fg * c + ig * tanh_apx(zg);
                h = og * tanh_apx(c);

                // broadcast h into every cluster CTA's hbuf[s&1]
                uint32_t dst = smem_u32(&hbuf[s & 1][cbase + j]);
#pragma unroll
                for (int p = 0; p < CSIZE; p++) st_cluster_f32(dst, (uint32_t)p, h);
            }
            __syncwarp();
            if (lane < CSIZE) arrive_cluster((s & 1) ? bar1 : bar0, (uint32_t)lane);

            // global store AFTER the arrives (not on the release path)
            if (lane < 16)
                xnext[(size_t)t * Hn + dir * HDn + cbase + lane] = h;
        }
    }

    asm volatile("barrier.cluster.arrive.aligned;" ::: "memory");
    asm volatile("barrier.cluster.wait.aligned;" ::: "memory");
}

// ---------------- projection: feats = x2 @ W_out^T + b_out ----------------
__global__ void proj_kernel(const float* __restrict__ Wout,
                            const float* __restrict__ bout) {
    int t = blockIdx.x;
    __shared__ float xs[Hn];
    int tid = threadIdx.x;   // 160
    for (int i = tid; i < Hn; i += 160) xs[i] = g_x2[(long)t * Hn + i];
    __syncthreads();
    int tag = tid >> 3;      // 0..19
    int p = tid & 7;
    float sum = 0.f;
    const float* wr = Wout + (long)tag * Hn + p * 64;
    const float* xr = xs + p * 64;
#pragma unroll
    for (int i = 0; i < 64; i++) sum = fmaf(__ldg(&wr[i]), xr[i], sum);
    sum += __shfl_xor_sync(0xffffffffu, sum, 1);
    sum += __shfl_xor_sync(0xffffffffu, sum, 2);
    sum += __shfl_xor_sync(0xffffffffu, sum, 4);
    if (p == 0) g_feats[t * NTAGS + tag] = sum + __ldg(&bout[tag]);
}

// ---------------- Viterbi: one warp; feats preloaded into smem; tree argmax ---
// Dynamic smem: feats copy (160 KB) + backpointers (40 KB).
#define VSMEM_BYTES (Tn * NTAGS * 4 + Tn * NTAGS)
__global__ void viterbi_kernel(const float* __restrict__ trans,
                               float* __restrict__ out, int out_size) {
    extern __shared__ unsigned char vsm[];
    float* fs = (float*)vsm;                          // [Tn][NTAGS]
    unsigned char* bp = vsm + Tn * NTAGS * 4;         // [Tn][NTAGS]

    int n = threadIdx.x;                              // 0..31
    // preload all feats into smem (off the sequential chain)
    for (int i = n; i < Tn * NTAGS; i += 32) fs[i] = __ldg(&g_feats[i]);

    bool act = (n < NTAGS);
    float tr[NTAGS];
#pragma unroll
    for (int p = 0; p < NTAGS; p++) tr[p] = act ? __ldg(&trans[n * NTAGS + p]) : 0.f;
    float trE = act ? __ldg(&trans[ENDT * NTAGS + n]) : 0.f;
    float v = act ? ((n == STARTT) ? 0.f : NEGV) : -1e30f;
    __syncwarp();

    for (int t = 0; t < Tn; t++) {
        float sc[NTAGS];
#pragma unroll
        for (int p = 0; p < NTAGS; p++)
            sc[p] = __shfl_sync(0xffffffffu, v, p) + tr[p];

        // adjacent-pair argmax tree (first-index semantics preserved)
        float mv[10]; int mi_[10];
#pragma unroll
        for (int i = 0; i < 10; i++) {
            bool left = sc[2 * i] >= sc[2 * i + 1];
            mv[i] = left ? sc[2 * i] : sc[2 * i + 1];
            mi_[i] = left ? 2 * i : 2 * i + 1;
        }
#pragma unroll
        for (int i = 0; i < 5; i++) {
            bool left = mv[2 * i] >= mv[2 * i + 1];
            mv[i] = left ? mv[2 * i] : mv[2 * i + 1];
            mi_[i] = left ? mi_[2 * i] : mi_[2 * i + 1];
        }
        {
            bool l0 = mv[0] >= mv[1];
            float v0 = l0 ? mv[0] : mv[1]; int i0 = l0 ? mi_[0] : mi_[1];
            bool l1 = mv[2] >= mv[3];
            float v1 = l1 ? mv[2] : mv[3]; int i1 = l1 ? mi_[2] : mi_[3];
            bool l2 = v0 >= v1;
            float v2 = l2 ? v0 : v1; int i2 = l2 ? i0 : i1;
            bool l3 = v2 >= mv[4];
            mv[0] = l3 ? v2 : mv[4]; mi_[0] = l3 ? i2 : mi_[4];
        }
        float feat = act ? fs[t * NTAGS + n] : 0.f;
        v = mv[0] + feat;
        if (act) bp[t * NTAGS + n] = (unsigned char)mi_[0];
    }

    float term = act ? (v + trE) : -1e30f;
    int idx = act ? n : 31;
#pragma unroll
    for (int off = 16; off; off >>= 1) {
        float ov = __shfl_xor_sync(0xffffffffu, term, off);
        int oi = __shfl_xor_sync(0xffffffffu, idx, off);
        if (ov > term || (ov == term && oi < idx)) { term = ov; idx = oi; }
    }
    __syncwarp();

    if (n == 0) {
        if (out_size > 0) out[0] = term;
        int tag = idx;
        for (int t = Tn - 1; t >= 0; t--) {
            if (1 + t < out_size) out[1 + t] = (float)tag;
            tag = bp[t * NTAGS + tag];
        }
        for (int i = Tn + 1; i < out_size; i++) out[i] = 0.f;
    }
}

// ---------------- launch ----------------
extern "C" void kernel_launch(void* const* d_in, const int* in_sizes, int n_in,
                              void* d_out, int out_size) {
    const int*   sent    = (const int*)d_in[0];
    const float* emb     = (const float*)d_in[1];
    const float* l0f_Wih = (const float*)d_in[2];
    const float* l0f_Whh = (const float*)d_in[3];
    const float* l0f_bih = (const float*)d_in[4];
    const float* l0f_bhh = (const float*)d_in[5];
    const float* l0b_Wih = (const float*)d_in[6];
    const float* l0b_Whh = (const float*)d_in[7];
    const float* l0b_bih = (const float*)d_in[8];
    const float* l0b_bhh = (const float*)d_in[9];
    const float* l1f_Wih = (const float*)d_in[10];
    const float* l1f_Whh = (const float*)d_in[11];
    const float* l1f_bih = (const float*)d_in[12];
    const float* l1f_bhh = (const float*)d_in[13];
    const float* l1b_Wih = (const float*)d_in[14];
    const float* l1b_Whh = (const float*)d_in[15];
    const float* l1b_bih = (const float*)d_in[16];
    const float* l1b_bhh = (const float*)d_in[17];
    const float* W_out   = (const float*)d_in[18];
    const float* b_out   = (const float*)d_in[19];
    const float* trans   = (const float*)d_in[20];
    float* out = (float*)d_out;

    static float* s_x1 = nullptr;
    static float* s_x2 = nullptr;
    static cudaStream_t s1 = nullptr;
    static cudaEvent_t ev0 = nullptr, ev1 = nullptr, ev2 = nullptr;
    if (!s_x1) {
        cudaGetSymbolAddress((void**)&s_x1, g_x1);
        cudaGetSymbolAddress((void**)&s_x2, g_x2);
        cudaStreamCreateWithFlags(&s1, cudaStreamNonBlocking);
        cudaEventCreateWithFlags(&ev0, cudaEventDisableTiming);
        cudaEventCreateWithFlags(&ev1, cudaEventDisableTiming);
        cudaEventCreateWithFlags(&ev2, cudaEventDisableTiming);
        cudaFuncSetAttribute(viterbi_kernel,
                             cudaFuncAttributeMaxDynamicSharedMemorySize, VSMEM_BYTES);
        cudaFuncSetAttribute(recur_kernel,
                             cudaFuncAttributeNonPortableClusterSizeAllowed, 1);
    }

    dim3 ggrid(8, 2, 16);   // n-tile, dir, mi (interleaved m-tiles)

    // stream 0 (captured): zero flags, then recurrences
    zero_flags_kernel<<<1, 64>>>();
    cudaEventRecord(ev0, 0);
    cudaStreamWaitEvent(s1, ev0, 0);

    // GEMM0 on side stream, concurrent with recur0 (flag-gated per tile)
    gemm_kernel<<<ggrid, 256, 0, s1>>>(0, nullptr, sent, emb, l0f_Wih, l0b_Wih,
                                       l0f_bih, l0f_bhh, l0b_bih, l0b_bhh);
    recur_kernel<<<2 * CSIZE, RTHREADS>>>(0, l0f_Whh, l0b_Whh, s_x1);

    // GEMM1 must wait for x1 (recur0 done), then runs concurrent with recur1
    cudaEventRecord(ev1, 0);
    cudaStreamWaitEvent(s1, ev1, 0);
    gemm_kernel<<<ggrid, 256, 0, s1>>>(1, s_x1, nullptr, nullptr, l1f_Wih, l1b_Wih,
                                       l1f_bih, l1f_bhh, l1b_bih, l1b_bhh);
    cudaEventRecord(ev2, s1);

    recur_kernel<<<2 * CSIZE, RTHREADS>>>(1, l1f_Whh, l1b_Whh, s_x2);

    // join side stream back before epilogue
    cudaStreamWaitEvent(0, ev2, 0);
    proj_kernel<<<Tn, 160>>>(W_out, b_out);
    viterbi_kernel<<<1, 32, VSMEM_BYTES>>>(trans, out, out_size);
}